// round 12
// baseline (speedup 1.0000x reference)
#include <cuda_runtime.h>
#include <math.h>

#define NB 128
#define NK 64
#define NM 2048
#define NQD 128
#define NH 256
#define NC 32
#define HS 68      // padded row stride, float4-aligned
#define TM 64      // points per CTA
#define KT 16      // k-tile for weight staging

typedef unsigned long long ull;

// ---- scratch (no allocation allowed) ----
__device__ float d_inv[NB*NK];
__device__ float d_P[NB*NH];
__device__ float d_Qc[NM*NH];
__device__ float d_W2T[NH*NH];
__device__ float d_W3T[NH*NH];
__device__ float d_weff[NQD+1];
__device__ float d_c[NM];

__device__ __forceinline__ float gelu_f(float x){
    return 0.5f*x*(1.0f + erff(x*0.7071067811865475f));
}
__device__ __forceinline__ float warp_red_sum(float v){
    v += __shfl_xor_sync(0xffffffffu, v, 16);
    v += __shfl_xor_sync(0xffffffffu, v, 8);
    v += __shfl_xor_sync(0xffffffffu, v, 4);
    v += __shfl_xor_sync(0xffffffffu, v, 2);
    v += __shfl_xor_sync(0xffffffffu, v, 1);
    return v;
}
__device__ __forceinline__ float warp_red_max(float v){
    v = fmaxf(v, __shfl_xor_sync(0xffffffffu, v, 16));
    v = fmaxf(v, __shfl_xor_sync(0xffffffffu, v, 8));
    v = fmaxf(v, __shfl_xor_sync(0xffffffffu, v, 4));
    v = fmaxf(v, __shfl_xor_sync(0xffffffffu, v, 2));
    v = fmaxf(v, __shfl_xor_sync(0xffffffffu, v, 1));
    return v;
}

// ---- f32x2 packed-FMA helpers (FFMA2 is PTX-only) ----
__device__ __forceinline__ ull pack2(float x, float y){
    ull r; asm("mov.b64 %0, {%1, %2};" : "=l"(r) : "f"(x), "f"(y)); return r;
}
__device__ __forceinline__ ull dup2(float x){
    ull r; asm("mov.b64 %0, {%1, %1};" : "=l"(r) : "f"(x)); return r;
}
__device__ __forceinline__ void fma2(ull& d, ull a, ull b){
    asm("fma.rn.f32x2 %0, %1, %2, %0;" : "+l"(d) : "l"(a), "l"(b));
}
__device__ __forceinline__ float2 unpack2(ull v){
    float2 f; asm("mov.b64 {%0, %1}, %2;" : "=f"(f.x), "=f"(f.y) : "l"(v)); return f;
}

// ================= weff = qW^T kW (+ qb.kW), must precede k_prep =============
__global__ void k_weff(const float* __restrict__ qW, const float* __restrict__ qb,
                       const float* __restrict__ kW){
    int t = threadIdx.x;  // 128 threads
    float acc = 0.f;
    #pragma unroll 8
    for (int a=0;a<NQD;a++) acc += qW[a*NQD+t]*kW[a];
    d_weff[t] = acc;
    if (t == 0){
        float be = 0.f;
        for (int a=0;a<NQD;a++) be += qb[a]*kW[a];
        d_weff[NQD] = be;
    }
}

// ================= unified prep kernel (roles by blockIdx.x) =================
// [0,128)    transpose pm_W2  -> d_W2T
// [128,256)  transpose pm_W3  -> d_W3T
// [256,384)  per-batch inv / global MLP / P
// [384,388)  c[m] = (query[m].weff + beff)/sqrt(AD)   (512 m per block)
// [388,1412) Qc (2 queries per block)
__global__ void __launch_bounds__(512,1) k_prep(
    const float* __restrict__ g, const float* __restrict__ query,
    const float* __restrict__ gW1, const float* __restrict__ gb1,
    const float* __restrict__ gW2, const float* __restrict__ gb2,
    const float* __restrict__ gW3, const float* __restrict__ gb3,
    const float* __restrict__ pW1, const float* __restrict__ pb1,
    const float* __restrict__ pW2, const float* __restrict__ pW3)
{
    __shared__ float sb[1088];
    int blk = blockIdx.x, tid = threadIdx.x;

    if (blk < 128){
        int idx = blk*512 + tid;
        d_W2T[idx] = pW2[(idx & 255)*NH + (idx >> 8)];
    } else if (blk < 256){
        int idx = (blk-128)*512 + tid;
        d_W3T[idx] = pW3[(idx & 255)*NH + (idx >> 8)];
    } else if (blk < 384){
        int b = blk - 256;
        float* inv_s = sb;
        float* h1 = sb + 64;
        float* h2 = sb + 320;
        float* h3 = sb + 576;
        if (tid < NK){
            const float* gp = g + ((size_t)b*NK + tid)*3;
            float v = sqrtf(gp[0]*gp[0] + gp[1]*gp[1] + gp[2]*gp[2]);
            inv_s[tid] = v;
            d_inv[b*NK + tid] = v;
        }
        __syncthreads();
        if (tid < NH){
            float acc = gb1[tid];
            const float* wr = gW1 + tid*NK;
            #pragma unroll 8
            for (int k=0;k<NK;k++) acc += wr[k]*inv_s[k];
            h1[tid] = gelu_f(acc);
        }
        __syncthreads();
        if (tid < NH){
            float acc = gb2[tid];
            const float* wr = gW2 + tid*NH;
            #pragma unroll 8
            for (int k=0;k<NH;k++) acc += wr[k]*h1[k];
            h2[tid] = gelu_f(acc);
        }
        __syncthreads();
        if (tid < NH){
            float acc = gb3[tid];
            const float* wr = gW3 + tid*NH;
            #pragma unroll 8
            for (int k=0;k<NH;k++) acc += wr[k]*h2[k];
            h3[tid] = acc;
        }
        __syncthreads();
        if (tid < NH){
            float acc = pb1[tid];
            const float* wr = pW1 + (size_t)tid*385;
            #pragma unroll 8
            for (int k=0;k<NH;k++) acc += wr[k]*h3[k];
            d_P[b*NH + tid] = acc;
        }
    } else if (blk < 388){
        // c[m]: 16 warps x 32 m each = 512 m per block
        float* weff_s = sb;                 // 129
        if (tid < NQD+1) weff_s[tid] = d_weff[tid];
        __syncthreads();
        int wv = tid >> 5, lid = tid & 31;
        float w0 = weff_s[lid],    w1 = weff_s[lid+32];
        float w2 = weff_s[lid+64], w3 = weff_s[lid+96];
        float be = weff_s[NQD];
        int mbase = (blk-384)*512 + wv*32;
        for (int it=0; it<32; it++){
            int m = mbase + it;
            const float* q = query + (size_t)m*NQD;
            float acc = q[lid]*w0 + q[lid+32]*w1 + q[lid+64]*w2 + q[lid+96]*w3;
            acc = warp_red_sum(acc);
            if (lid == 0) d_c[m] = (acc + be) * 0.08838834764831845f;
        }
    } else {
        int bq = blk - 388;
        float* q_s = sb;
        if (tid < 256)
            q_s[tid] = query[((size_t)bq*2 + (tid>>7))*NQD + (tid & 127)];
        __syncthreads();
        int h = tid >> 8;
        int wv = (tid >> 5) & 7;
        int lid = tid & 31;
        int m = bq*2 + h;
        const float* qs = q_s + h*128;
        for (int it=0; it<32; it++){
            int j = it*8 + wv;
            const float* row = pW1 + (size_t)j*385 + NH;
            float acc = row[lid]      * qs[lid]
                      + row[lid+32]   * qs[lid+32]
                      + row[lid+64]   * qs[lid+64]
                      + row[lid+96]   * qs[lid+96];
            acc = warp_red_sum(acc);
            if (lid == 0) d_Qc[(size_t)m*NH + j] = acc;
        }
    }
}

// ============ GEMM layer: 64 pts x 256 outs x 256 k, 512 threads =============
// Warp w: point-group (w&7)*8, col-half (w>>3)*128. Lane tx owns 4 cols.
// f32x2 accumulators: 4 row-pairs x 4 cols = 32 FMAs / 16 FFMA2 per k-step.
template<bool GELU>
__device__ __forceinline__ void gemm_layer(const float* __restrict__ hIn,
        float* __restrict__ wt, const float* __restrict__ WT,
        const float* __restrict__ bias, float* __restrict__ hOut, int tid){
    const int tx = tid & 31;
    const int wp = tid >> 5;              // 16 warps
    const int p0 = (wp & 7) << 3;         // 8 points
    const int ch = (wp >> 3) << 7;        // column half: 0 or 128
    ull acc[4][4];
    #pragma unroll
    for (int rp=0;rp<4;rp++)
        #pragma unroll
        for (int c=0;c<4;c++) acc[rp][c] = 0ull;

    {   // preload tile 0: 1024 float4 by 512 threads
        const float4* s = (const float4*)WT;
        float4* d = (float4*)wt;
        d[tid]     = s[tid];
        d[tid+512] = s[tid+512];
    }
    __syncthreads();

    for (int kt=0; kt<NH/KT; kt++){
        float4 r0, r1;
        if (kt < NH/KT-1){
            const float4* s = (const float4*)(WT + (kt+1)*KT*NH);
            r0 = s[tid]; r1 = s[tid+512];
        }
        const float* buf = wt + (kt & 1)*(KT*NH);
        #pragma unroll
        for (int t=0;t<KT;t++){
            const float* arow = hIn + (kt*KT+t)*HS + p0;
            float4 a0 = *(const float4*)(arow);
            float4 a1 = *(const float4*)(arow+4);
            ull A[4] = {pack2(a0.x,a0.y), pack2(a0.z,a0.w),
                        pack2(a1.x,a1.y), pack2(a1.z,a1.w)};
            const float* brow = buf + t*NH + ch + tx;
            #pragma unroll
            for (int c=0;c<4;c++){
                ull B = dup2(brow[c*32]);       // stride-1 across lanes
                #pragma unroll
                for (int rp=0;rp<4;rp++) fma2(acc[rp][c], A[rp], B);
            }
        }
        if (kt < NH/KT-1){
            float4* d = (float4*)(wt + ((kt+1) & 1)*(KT*NH));
            d[tid]     = r0;
            d[tid+512] = r1;
        }
        __syncthreads();
    }

    #pragma unroll
    for (int c=0;c<4;c++){
        int col = ch + c*32 + tx;
        float bv = bias[col];
        float v[8];
        #pragma unroll
        for (int rp=0;rp<4;rp++){
            float2 f = unpack2(acc[rp][c]);
            v[rp*2]   = f.x + bv;
            v[rp*2+1] = f.y + bv;
        }
        if (GELU){
            #pragma unroll
            for (int i=0;i<8;i++) v[i] = gelu_f(v[i]);
        }
        *(float4*)(hOut + col*HS + p0)     = make_float4(v[0],v[1],v[2],v[3]);
        *(float4*)(hOut + col*HS + p0 + 4) = make_float4(v[4],v[5],v[6],v[7]);
    }
    __syncthreads();
}

// ================= fused main: 512 threads =================
__global__ void __launch_bounds__(512, 1)
k_main(const float* __restrict__ g, const float* __restrict__ pW1,
       const float* __restrict__ pb2, const float* __restrict__ pb3,
       const float* __restrict__ tW, const float* __restrict__ tb,
       const float* __restrict__ wW, const float* __restrict__ wb,
       const float* __restrict__ cW, const float* __restrict__ cb,
       float* __restrict__ out){
    extern __shared__ float sm[];
    float* hA     = sm;                   // [256][HS]
    float* hB     = hA + NH*HS;           // [256][HS]  (also head-weight stage)
    float* wt     = hB + NH*HS;           // [2][KT*NH]
    float* inv_s  = wt + 2*KT*NH;         // 64
    float* ainv_s = inv_s + 64;           // 64
    float* y0_s   = ainv_s + 64;          // 192
    float* g_s    = y0_s + 192;           // 192
    float* P_s    = g_s + 192;            // 256
    float* w1c_s  = P_s + 256;            // 256
    float* c_s    = w1c_s + 256;          // 64

    int tid = threadIdx.x;
    int b = blockIdx.y;
    int m0 = blockIdx.x * TM;
    int lid = tid & 31, w = tid >> 5;     // 16 warps

    if (tid < 64)                 inv_s[tid]  = d_inv[b*NK + tid];
    if (tid >= 64 && tid < 256)   g_s[tid-64] = g[(size_t)b*NK*3 + (tid-64)];
    if (tid < 256){
        P_s[tid]   = d_P[b*NH + tid];
        w1c_s[tid] = pW1[(size_t)tid*385 + 384];
    }
    if (tid >= 256 && tid < 320)  c_s[tid-256] = d_c[m0 + tid - 256];
    __syncthreads();

    // ---- attention: warp-cooperative softmax, 4 points per warp ----
    {
        float i1 = inv_s[lid], i2 = inv_s[lid+32];
        float gx0 = g_s[lid*3],      gx1 = g_s[lid*3+1],      gx2 = g_s[lid*3+2];
        float gy0 = g_s[(lid+32)*3], gy1 = g_s[(lid+32)*3+1], gy2 = g_s[(lid+32)*3+2];
        #pragma unroll
        for (int i=0;i<4;i++){
            int p = w*4 + i;
            float cm = c_s[p];
            float t1 = cm*i1, t2 = cm*i2;
            float mx = warp_red_max(fmaxf(t1, t2));
            float e1 = expf(t1 - mx), e2 = expf(t2 - mx);
            float s  = warp_red_sum(e1 + e2);
            float a0 = warp_red_sum(e1*gx0 + e2*gy0);
            float a1 = warp_red_sum(e1*gx1 + e2*gy1);
            float a2 = warp_red_sum(e1*gx2 + e2*gy2);
            float ai = warp_red_sum(e1*i1 + e2*i2);
            if (lid == 0){
                float r = 1.f/s;
                y0_s[p*3+0] = a0*r; y0_s[p*3+1] = a1*r; y0_s[p*3+2] = a2*r;
                ainv_s[p] = ai*r;
            }
        }
    }
    __syncthreads();

    // ---- layer 1 (separable): hA[j][p] = gelu(P[j] + Qc[m][j] + w1c[j]*ainv[p]) ----
    {
        int j = tid & 255, h = tid >> 8, pb = h*32;
        float Pv = P_s[j], wc = w1c_s[j];
        const float* qc = d_Qc + (size_t)(m0+pb)*NH + j;  // coalesced across j
        float* row = hA + j*HS + pb;
        for (int p=0;p<32;p+=4){
            float4 v;
            v.x = gelu_f(Pv + qc[(size_t)(p+0)*NH] + wc*ainv_s[pb+p+0]);
            v.y = gelu_f(Pv + qc[(size_t)(p+1)*NH] + wc*ainv_s[pb+p+1]);
            v.z = gelu_f(Pv + qc[(size_t)(p+2)*NH] + wc*ainv_s[pb+p+2]);
            v.w = gelu_f(Pv + qc[(size_t)(p+3)*NH] + wc*ainv_s[pb+p+3]);
            *(float4*)(row + p) = v;
        }
    }
    __syncthreads();

    // ---- layer 2 + layer 3 ----
    gemm_layer<true >(hA, wt, d_W2T, pb2, hB, tid);
    gemm_layer<false>(hB, wt, d_W3T, pb3, hA, tid);    // s in hA[j][p]

    // ---- stage head weights into hB: hw[j*40 + o], o<34 ----
    {
        int j = tid & 255, h = tid >> 8;
        #pragma unroll
        for (int o=h*17; o<h*17+17; o++){
            float v = (o < 32) ? tW[o*NH + j] : ((o == 32) ? wW[j] : cW[j]);
            hB[j*40 + o] = v;
        }
    }
    __syncthreads();

    // ---- heads: lane owns point-pair, warp owns 2 type-cols (+extras on w<2) ----
    {
        int pp = lid*2;
        ull acc0 = 0ull, acc1 = 0ull, accx = 0ull;
        int c0 = w*2;
        int xcol = 32 + w;                 // valid for w<2
        #pragma unroll 4
        for (int j=0;j<NH;j++){
            ull Ap = *(const ull*)(hA + j*HS + pp);      // lane-pair, conflict-free
            const float* hw = hB + j*40;
            fma2(acc0, Ap, dup2(hw[c0]));
            fma2(acc1, Ap, dup2(hw[c0+1]));
            if (w < 2) fma2(accx, Ap, dup2(hw[xcol]));
        }
        size_t base = (size_t)b*NM + m0;
        float* outT = out + (size_t)NB*NM*3;
        {
            float bv0 = tb[c0], bv1 = tb[c0+1];
            float2 f0 = unpack2(acc0), f1 = unpack2(acc1);
            float* o0 = outT + (base + pp)*NC;
            o0[c0]        = f0.x + bv0;
            o0[c0+1]      = f1.x + bv1;
            o0[NC + c0]   = f0.y + bv0;
            o0[NC + c0+1] = f1.y + bv1;
        }
        if (w == 0){                      // weight-logit head
            float* outW = out + (size_t)NB*NM*3 + (size_t)NB*NM*NC;
            float2 f = unpack2(accx);
            outW[base + pp    ] = f.x + wb[0];
            outW[base + pp + 1] = f.y + wb[0];
        }
        if (w == 1){                      // gate head -> y outputs
            float2 f = unpack2(accx);
            float cbv = cb[0];
            #pragma unroll
            for (int i=0;i<2;i++){
                int p = pp + i;
                float gate = 1.f/(1.f + expf(-((i ? f.y : f.x) + cbv)));
                size_t pi = base + p;
                out[pi*3+0] = y0_s[p*3+0]*gate;
                out[pi*3+1] = y0_s[p*3+1]*gate;
                out[pi*3+2] = y0_s[p*3+2]*gate;
            }
        }
    }
}

// ================= launch =================
extern "C" void kernel_launch(void* const* d_in, const int* in_sizes, int n_in,
                              void* d_out, int out_size){
    const float* g    = (const float*)d_in[0];
    const float* query= (const float*)d_in[1];
    const float* qW   = (const float*)d_in[2];
    const float* qb   = (const float*)d_in[3];
    const float* kW   = (const float*)d_in[4];
    // d_in[5] = kb: cancels in softmax (constant over k)
    const float* gW1  = (const float*)d_in[6];
    const float* gb1  = (const float*)d_in[7];
    const float* gW2  = (const float*)d_in[8];
    const float* gb2  = (const float*)d_in[9];
    const float* gW3  = (const float*)d_in[10];
    const float* gb3  = (const float*)d_in[11];
    const float* pW1  = (const float*)d_in[12];
    const float* pb1  = (const float*)d_in[13];
    const float* pW2  = (const float*)d_in[14];
    const float* pb2  = (const float*)d_in[15];
    const float* pW3  = (const float*)d_in[16];
    const float* pb3  = (const float*)d_in[17];
    const float* tW   = (const float*)d_in[18];
    const float* tb   = (const float*)d_in[19];
    const float* wW   = (const float*)d_in[20];
    const float* wb   = (const float*)d_in[21];
    const float* cW   = (const float*)d_in[22];
    const float* cb   = (const float*)d_in[23];
    float* out = (float*)d_out;

    const int SMEM_MAIN = (2*NH*HS + 2*KT*NH + 64 + 64 + 192 + 192 + 256 + 256 + 64) * 4;
    cudaFuncSetAttribute(k_main, cudaFuncAttributeMaxDynamicSharedMemorySize, SMEM_MAIN);

    k_weff<<<1, 128>>>(qW, qb, kW);
    k_prep<<<1412, 512>>>(g, query,
                          gW1, gb1, gW2, gb2, gW3, gb3,
                          pW1, pb1, pW2, pW3);
    k_main<<<dim3(NM/TM, NB), 512, SMEM_MAIN>>>(g, pW1, pb2, pb3,
                                                tW, tb, wW, wb, cW, cb, out);
}